// round 7
// baseline (speedup 1.0000x reference)
#include <cuda_runtime.h>
#include <cuda_bf16.h>
#include <cstdint>

// ============================================================================
// out = BN(scale * (x @ W^T)) -- baseline-PTX version (target sm_103, no 'a'):
// tcgen05 unavailable -> mma.sync.m16n8k16 bf16 (legacy HMMA) + ldmatrix +
// cp.async. 3-term bf16 RN split: x*w ~= xh*wh + xl*wh + xh*wl (~1e-5 rel).
// Phase 1: split fp32 -> (hi|lo) bf16 scratch. Phase 2: GEMM 128x256 tiles,
// 512 thr, warp tile 64x32, K-chunk 32, 4-stage cp.async pipeline.
// ============================================================================

#define B_DIM   4096
#define IN_DIM  2048
#define OUT_DIM 2048
#define KP      4096              // packed K per matrix: [hi(2048) | lo(2048)]
#define EPSV    1e-5f

#define TM 128
#define TN 256
#define THREADS 512
#define NCHT 192                  // 3 terms * (2048/32) chunks, K-chunk = 32 bf16

#define ROWB 80                   // padded smem row: 64B data + 16B (conflict-free)
#define SA_BYTES (128 * ROWB)     // 10240
#define SB_BYTES (256 * ROWB)     // 20480
#define STAGE_SZ (SA_BYTES + SB_BYTES)   // 30720
#define OFF_CA 0
#define OFF_CB 1024
#define OFF_ST 2048
#define SMEM_BYTES (OFF_ST + 4 * STAGE_SZ)   // 124928

// Split bf16 scratch: [row][hi 2048 | lo 2048]
__device__ __align__(16) __nv_bfloat16 g_A[(size_t)B_DIM * KP];     // 32 MB
__device__ __align__(16) __nv_bfloat16 g_B[(size_t)OUT_DIM * KP];   // 16 MB

// ---------------------------------------------------------------- helpers
static __device__ __forceinline__ uint32_t smem_u32(const void* p) {
    uint32_t a;
    asm("{ .reg .u64 t; cvta.to.shared.u64 t, %1; cvt.u32.u64 %0, t; }" : "=r"(a) : "l"(p));
    return a;
}

#define CP_ASYNC16(dst, src) \
    asm volatile("cp.async.cg.shared.global [%0], [%1], 16;" :: "r"(dst), "l"(src))
#define CP_COMMIT() asm volatile("cp.async.commit_group;" ::: "memory")
#define CP_WAIT2()  asm volatile("cp.async.wait_group 2;" ::: "memory")

#define LDSM4(r, addr) \
    asm volatile("ldmatrix.sync.aligned.m8n8.x4.shared.b16 {%0,%1,%2,%3}, [%4];" \
                 : "=r"((r)[0]), "=r"((r)[1]), "=r"((r)[2]), "=r"((r)[3]) : "r"(addr))

#define MMA16816(d, a, b0, b1) \
    asm volatile("mma.sync.aligned.m16n8k16.row.col.f32.bf16.bf16.f32 " \
                 "{%0,%1,%2,%3}, {%4,%5,%6,%7}, {%8,%9}, {%0,%1,%2,%3};" \
                 : "+f"((d)[0]), "+f"((d)[1]), "+f"((d)[2]), "+f"((d)[3]) \
                 : "r"((a)[0]), "r"((a)[1]), "r"((a)[2]), "r"((a)[3]), \
                   "r"(b0), "r"(b1))

// bf16x2 RN pack: memory-order lo halfword = a, hi halfword = b
static __device__ __forceinline__ uint32_t pack2(float a, float b) {
    uint32_t r;
    asm("cvt.rn.bf16x2.f32 %0, %1, %2;" : "=r"(r) : "f"(b), "f"(a));
    return r;
}

// RN split: xh = RN_bf16(x); xl = RN_bf16(x - xh)  (residual exact, zero-mean)
struct Split4 { uint32_t h0, h1, l0, l1; };
static __device__ __forceinline__ Split4 split4(float4 v) {
    Split4 r;
    r.h0 = pack2(v.x, v.y);
    r.h1 = pack2(v.z, v.w);
    float hx = __uint_as_float(r.h0 << 16);
    float hy = __uint_as_float(r.h0 & 0xFFFF0000u);
    float hz = __uint_as_float(r.h1 << 16);
    float hw = __uint_as_float(r.h1 & 0xFFFF0000u);
    r.l0 = pack2(v.x - hx, v.y - hy);
    r.l1 = pack2(v.z - hz, v.w - hw);
    return r;
}

// ---------------------------------------------------------------- split kernels
__global__ void cvt_kernel(const float* __restrict__ src, int which, int total) {
    __nv_bfloat16* dst = which ? g_B : g_A;
    int64_t i = ((int64_t)blockIdx.x * blockDim.x + threadIdx.x) * 4;
    if (i >= total) return;
    int64_t r = i >> 11;           // source row (IN_DIM = 2048 cols)
    int c = (int)(i & 2047);
    float4 v = *reinterpret_cast<const float4*>(src + i);
    Split4 sp = split4(v);
    *reinterpret_cast<uint2*>(dst + (r << 12) + c)        = make_uint2(sp.h0, sp.h1);
    *reinterpret_cast<uint2*>(dst + (r << 12) + 2048 + c) = make_uint2(sp.l0, sp.l1);
}

// ---------------------------------------------------------------- GEMM kernel
__global__ __launch_bounds__(THREADS, 1) void gemm_bn_kernel(
    const float* __restrict__ scale, const float* __restrict__ mean,
    const float* __restrict__ var, const float* __restrict__ gamma,
    const float* __restrict__ beta, float* __restrict__ out) {
    extern __shared__ __align__(16) char smem[];
    const uint32_t sb = smem_u32(smem);
    const int tid = threadIdx.x, wid = tid >> 5, lane = tid & 31;
    const int warp_m = wid & 1;        // 2 warps over M (64 each)
    const int warp_n = wid >> 1;       // 8 warps over N (32 each)
    const int rowg = blockIdx.x * TM;
    const int colg = blockIdx.y * TN;

    // BN coefficients: out = acc * As[col] + Bs[col]
    if (tid < TN) {
        int cg = colg + tid;
        float ga = gamma[cg], sc = scale[cg], mu = mean[cg], be = beta[cg];
        float inv = rsqrtf(var[cg] + EPSV);
        reinterpret_cast<float*>(smem + OFF_CA)[tid] = ga * sc * inv;
        reinterpret_cast<float*>(smem + OFF_CB)[tid] = be - ga * mu * inv;
    }

    float acc[4][4][4];
#pragma unroll
    for (int mt = 0; mt < 4; mt++)
#pragma unroll
        for (int nt = 0; nt < 4; nt++)
#pragma unroll
            for (int e = 0; e < 4; e++) acc[mt][nt][e] = 0.0f;

    // chunk c in [0,192): term t = c/64, K-offset kk = (c%64)*32
    // t0: Ah*Bh, t1: Al*Bh, t2: Ah*Bl
    auto issue = [&](int ch, int st) {
        int t = ch >> 6, kk = (ch & 63) * 32;
        const __nv_bfloat16* asrc = g_A + (size_t)rowg * KP + ((t == 1) ? 2048 : 0) + kk;
        const __nv_bfloat16* bsrc = g_B + (size_t)colg * KP + ((t == 2) ? 2048 : 0) + kk;
        uint32_t abase = sb + OFF_ST + st * STAGE_SZ;
        uint32_t bbase = abase + SA_BYTES;
        {   // A: 128 rows x 4 x 16B, 1 per thread
            int row = tid >> 2, seg = tid & 3;
            CP_ASYNC16(abase + row * ROWB + seg * 16, asrc + (size_t)row * KP + seg * 8);
        }
#pragma unroll
        for (int j = 0; j < 2; j++) {   // B: 256 rows x 4 x 16B, 2 per thread
            int idx = tid + j * THREADS;
            int row = idx >> 2, seg = idx & 3;
            CP_ASYNC16(bbase + row * ROWB + seg * 16, bsrc + (size_t)row * KP + seg * 8);
        }
        CP_COMMIT();
    };

    issue(0, 0); issue(1, 1); issue(2, 2);

#pragma unroll 1
    for (int u = 0; u < NCHT; u++) {
        CP_WAIT2();                 // group u done (<=2 newest pending)
        __syncthreads();            // all warps done with stage being overwritten
        int nc = u + 3;
        issue(nc < NCHT ? nc : 0, nc & 3);   // tail: dummy refill, never consumed

        uint32_t abase = sb + OFF_ST + (u & 3) * STAGE_SZ;
        uint32_t bbase = abase + SA_BYTES;
#pragma unroll
        for (int ks = 0; ks < 2; ks++) {
            int kcolb = (ks * 16 + (lane >> 4) * 8) * 2;   // k-byte offset per lane group
            uint32_t a[4][4], b[2][4];
#pragma unroll
            for (int mt = 0; mt < 4; mt++) {
                uint32_t addr = abase + (warp_m * 64 + mt * 16 + (lane & 15)) * ROWB + kcolb;
                LDSM4(a[mt], addr);
            }
#pragma unroll
            for (int np = 0; np < 2; np++) {
                uint32_t addr = bbase + (warp_n * 32 + np * 16 + (lane & 15)) * ROWB + kcolb;
                LDSM4(b[np], addr);
            }
#pragma unroll
            for (int mt = 0; mt < 4; mt++)
#pragma unroll
                for (int nt = 0; nt < 4; nt++)
                    MMA16816(acc[mt][nt], a[mt],
                             b[nt >> 1][nt & 1], b[nt >> 1][2 + (nt & 1)]);
        }
    }

    // ---- epilogue: BN apply from registers, direct store ----
    const float* As = reinterpret_cast<const float*>(smem + OFF_CA);
    const float* Bs = reinterpret_cast<const float*>(smem + OFF_CB);
    const int r0 = lane >> 2, c0 = (lane & 3) * 2;
#pragma unroll
    for (int mt = 0; mt < 4; mt++) {
        int gr = rowg + warp_m * 64 + mt * 16 + r0;
#pragma unroll
        for (int nt = 0; nt < 4; nt++) {
            int lc = warp_n * 32 + nt * 8 + c0;
            float a0 = As[lc], a1 = As[lc + 1];
            float b0 = Bs[lc], b1 = Bs[lc + 1];
            float2 v0 = make_float2(acc[mt][nt][0] * a0 + b0, acc[mt][nt][1] * a1 + b1);
            float2 v1 = make_float2(acc[mt][nt][2] * a0 + b0, acc[mt][nt][3] * a1 + b1);
            *reinterpret_cast<float2*>(out + (size_t)gr * OUT_DIM + colg + lc) = v0;
            *reinterpret_cast<float2*>(out + (size_t)(gr + 8) * OUT_DIM + colg + lc) = v1;
        }
    }
}

// ---------------------------------------------------------------- launch
extern "C" void kernel_launch(void* const* d_in, const int* in_sizes, int n_in,
                              void* d_out, int out_size) {
    const float* x     = (const float*)d_in[0];
    const float* w     = (const float*)d_in[1];
    const float* scale = (const float*)d_in[2];
    const float* mean  = (const float*)d_in[3];
    const float* var   = (const float*)d_in[4];
    const float* gamma = (const float*)d_in[5];
    const float* beta  = (const float*)d_in[6];
    float* out = (float*)d_out;

    cudaFuncSetAttribute(gemm_bn_kernel,
                         cudaFuncAttributeMaxDynamicSharedMemorySize, SMEM_BYTES);

    int total_x = B_DIM * IN_DIM;          // 8388608
    int total_w = OUT_DIM * IN_DIM;        // 4194304
    cvt_kernel<<<total_x / (256 * 4), 256>>>(x, 0, total_x);
    cvt_kernel<<<total_w / (256 * 4), 256>>>(w, 1, total_w);

    dim3 grid(B_DIM / TM, OUT_DIM / TN);   // 32 x 8 = 256 CTAs
    gemm_bn_kernel<<<grid, THREADS, SMEM_BYTES>>>(scale, mean, var, gamma, beta, out);
}